// round 1
// baseline (speedup 1.0000x reference)
#include <cuda_runtime.h>

// SharedGroupLinearLayer: N=262144 tokens, DIN=DOUT=64, NT=2 templates.
// out = (x·W1^T + b1) + a0 * (x·(W0-W1)^T + (b0-b1)),  a0 = sigmoid(x·(rw0-rw1))
//
// Mapping: block = 256 threads = 2 groups of 4 warps. Each group processes one
// token at a time from a 64-token SMEM tile. Within the 4 warps of a group,
// each lane owns one (output o, row) slot: o = (warp%4)*16 + (lane&15),
// row = lane>>4 (row0 = W1, row1 = W0-W1). Weights are register-resident
// (64 floats/thread). Inner dot uses packed fma.rn.f32x2 (FFMA2).

#define NBB   16
#define DIN   64
#define DOUT  64
#define NTOK  (2048 * 8 * NBB)      // 262144
#define TILE  64
#define NTILES (NTOK / TILE)        // 4096

__device__ __forceinline__ void ffma2(unsigned long long &acc,
                                      unsigned long long a,
                                      unsigned long long b) {
    asm("fma.rn.f32x2 %0, %1, %2, %0;" : "+l"(acc) : "l"(a), "l"(b));
}
__device__ __forceinline__ unsigned long long pack2(float x, float y) {
    unsigned long long r;
    asm("mov.b64 %0, {%1, %2};" : "=l"(r) : "f"(x), "f"(y));
    return r;
}
__device__ __forceinline__ float2 unpack2(unsigned long long v) {
    float2 r;
    asm("mov.b64 {%0, %1}, %2;" : "=f"(r.x), "=f"(r.y) : "l"(v));
    return r;
}

__global__ __launch_bounds__(256, 2)
void sgl_kernel(const float* __restrict__ x,
                const float* __restrict__ emb,
                const float* __restrict__ read_w,
                const float* __restrict__ w_stack,
                const float* __restrict__ b_stack,
                float* __restrict__ out)
{
    __shared__ __align__(16) float xs[TILE * DIN];      // 16 KB token tile (emb added)
    __shared__ __align__(16) float s_emb[NBB * DIN];    // 4 KB
    __shared__ __align__(16) float s_rwd[DIN];          // rw0 - rw1
    __shared__ float s_a0[TILE];                        // per-token gate

    const int tid  = threadIdx.x;
    const int lane = tid & 31;
    const int wid  = tid >> 5;
    const int g    = wid >> 2;               // token sub-group (0 or 1)
    const int o    = (wid & 3) * 16 + (lane & 15);
    const int row  = lane >> 4;              // 0: W1, 1: W0-W1

    // one-time preload: embedding + routing-weight difference into SMEM
    for (int k = tid; k < NBB * DIN; k += 256) s_emb[k] = emb[k];
    if (tid < DIN) s_rwd[tid] = read_w[tid * 2] - read_w[tid * 2 + 1];

    // register-resident weights for this lane's (o, row) slot, packed f32x2
    ulonglong2 wv[16];
    {
        const float4* w1p = (const float4*)(w_stack + DOUT * DIN + o * DIN);
        const float4* w0p = (const float4*)(w_stack + o * DIN);
        #pragma unroll
        for (int j = 0; j < 16; j++) {
            float4 a = w1p[j];
            if (row) {
                float4 b0 = w0p[j];
                a.x = b0.x - a.x; a.y = b0.y - a.y;
                a.z = b0.z - a.z; a.w = b0.w - a.w;
            }
            wv[j].x = pack2(a.x, a.y);
            wv[j].y = pack2(a.z, a.w);
        }
    }
    const float b1o = b_stack[DOUT + o];
    const float bdo = b_stack[o] - b1o;

    __syncthreads();

    for (int tile = blockIdx.x; tile < NTILES; tile += gridDim.x)
    {
        const long tokBase = (long)tile * TILE;

        // ---- stage tile: 64 tokens x 64 floats, embedding pre-added ----
        {
            const float4* x4  = (const float4*)x + tokBase * (DIN / 4);
            const float4* e4  = (const float4*)s_emb;
            float4*       xs4 = (float4*)xs;
            #pragma unroll
            for (int k = 0; k < 4; k++) {
                int j = tid + k * 256;           // float4 index in tile
                int t = j >> 4, c = j & 15;      // token, chunk
                float4 v = x4[j];
                float4 e = e4[((t & 15) << 4) + c];  // nb = token%16 = t%16
                v.x += e.x; v.y += e.y; v.z += e.z; v.w += e.w;
                xs4[j] = v;
            }
        }
        __syncthreads();

        // ---- per-token gate: a0 = sigmoid(dot(xf, rw0-rw1)) ----
        {
            int t = tid >> 2, part = tid & 3;    // 4 threads per token
            const float4* xq = (const float4*)(xs + t * DIN) + part * 4;
            const float4* rq = (const float4*)s_rwd + part * 4;
            float l = 0.f;
            #pragma unroll
            for (int q = 0; q < 4; q++) {
                float4 xv = xq[q], rv = rq[q];
                l += xv.x * rv.x + xv.y * rv.y + xv.z * rv.z + xv.w * rv.w;
            }
            l += __shfl_xor_sync(0xffffffffu, l, 1);
            l += __shfl_xor_sync(0xffffffffu, l, 2);
            if (part == 0) s_a0[t] = 1.f / (1.f + expf(-l));
        }
        __syncthreads();

        // ---- main GEMV: each group of 4 warps walks its 32 tokens ----
        #pragma unroll 1
        for (int tt = 0; tt < 32; tt++) {
            const int t = g * 32 + tt;
            const ulonglong2* xp = (const ulonglong2*)(xs + t * DIN);
            unsigned long long acc0 = 0, acc1 = 0, acc2 = 0, acc3 = 0;
            #pragma unroll
            for (int j = 0; j < 16; j += 2) {
                ulonglong2 xa = xp[j];
                ulonglong2 xb = xp[j + 1];
                ffma2(acc0, xa.x, wv[j].x);
                ffma2(acc1, xa.y, wv[j].y);
                ffma2(acc2, xb.x, wv[j + 1].x);
                ffma2(acc3, xb.y, wv[j + 1].y);
            }
            float2 p0 = unpack2(acc0), p1 = unpack2(acc1);
            float2 p2 = unpack2(acc2), p3 = unpack2(acc3);
            float s = ((p0.x + p0.y) + (p1.x + p1.y))
                    + ((p2.x + p2.y) + (p3.x + p3.y));
            // row1 partner (W0-W1 dot) sits 16 lanes up
            float sd = __shfl_down_sync(0xffffffffu, s, 16);
            if (row == 0) {
                float a0  = s_a0[t];
                float res = fmaf(a0, sd + bdo, s + b1o);
                out[(tokBase + t) * DOUT + o] = res;
            }
        }
        __syncthreads();
    }
}

extern "C" void kernel_launch(void* const* d_in, const int* in_sizes, int n_in,
                              void* d_out, int out_size)
{
    const float* x       = (const float*)d_in[0];
    const float* emb     = (const float*)d_in[1];
    const float* read_w  = (const float*)d_in[2];
    const float* w_stack = (const float*)d_in[3];
    const float* b_stack = (const float*)d_in[4];
    float* out = (float*)d_out;

    // 2 blocks per SM (152 SMs on GB300); grid-stride over 4096 tiles
    sgl_kernel<<<304, 256>>>(x, emb, read_w, w_stack, b_stack, out);
}

// round 3
// speedup vs baseline: 2.3395x; 2.3395x over previous
#include <cuda_runtime.h>
#include <cuda_bf16.h>
#include <cstdint>

// SharedGroupLinearLayer via legacy mma.sync bf16 (split hi/lo, 3 passes).
// out = (x·W1^T + b1) + a0 * (x·(W0-W1)^T + (b0-b1)), a0 = sigmoid(x·(rw0-rw1))
// Per tile: D[128 tok, 128] = X[128,64] · Wcat^T, Wcat = [W1 ; W0-W1].
// x, Wcat split into bf16 hi+lo; D = xh·wh + xh·wl + xl·wh (err ~2^-18).
// Weights' B-fragments live in registers for the whole kernel (loaded once).

#define THREADS 256
#define TILE_M  128
#define NTILES  2048            // 262144 tokens / 128
#define GRID    152

__device__ __forceinline__ uint32_t smem_u32(const void* p) {
    uint32_t a;
    asm("{ .reg .u64 t; cvta.to.shared.u64 t, %1; cvt.u32.u64 %0, t; }" : "=r"(a) : "l"(p));
    return a;
}
// pack two f32 -> bf16x2 word: low 16 bits = lo arg, high = hi arg
__device__ __forceinline__ uint32_t cvt2bf(float lo, float hi) {
    uint32_t r;
    asm("cvt.rn.bf16x2.f32 %0, %1, %2;" : "=r"(r) : "f"(hi), "f"(lo));
    return r;
}
__device__ __forceinline__ void ldsm_x4(uint32_t* r, uint32_t addr) {
    asm volatile("ldmatrix.sync.aligned.m8n8.x4.shared.b16 {%0,%1,%2,%3}, [%4];"
        : "=r"(r[0]), "=r"(r[1]), "=r"(r[2]), "=r"(r[3]) : "r"(addr));
}
__device__ __forceinline__ void ldsm_x2(uint32_t* r, uint32_t addr) {
    asm volatile("ldmatrix.sync.aligned.m8n8.x2.shared.b16 {%0,%1}, [%2];"
        : "=r"(r[0]), "=r"(r[1]) : "r"(addr));
}
__device__ __forceinline__ void mma_bf16(float* d, const uint32_t* a, const uint32_t* b) {
    asm volatile("mma.sync.aligned.m16n8k16.row.col.f32.bf16.bf16.f32 "
        "{%0,%1,%2,%3}, {%4,%5,%6,%7}, {%8,%9}, {%0,%1,%2,%3};"
        : "+f"(d[0]), "+f"(d[1]), "+f"(d[2]), "+f"(d[3])
        : "r"(a[0]), "r"(a[1]), "r"(a[2]), "r"(a[3]), "r"(b[0]), "r"(b[1]));
}

__global__ __launch_bounds__(THREADS, 1)
void sgl_mma_kernel(const float* __restrict__ x,
                    const float* __restrict__ emb,
                    const float* __restrict__ read_w,
                    const float* __restrict__ w_stack,
                    const float* __restrict__ b_stack,
                    float* __restrict__ out)
{
    // ws: init phase = Wcat bf16 hi (16KB) + lo (16KB); main loop = A tile hi+lo
    __shared__ __align__(1024) char ws[32768];
    __shared__ __align__(16) float emb_s[16 * 64];
    __shared__ __align__(16) float rwd_s[64];
    __shared__ __align__(16) float b1_s[64];
    __shared__ __align__(16) float bd_s[64];
    __shared__ float logit_s[TILE_M];

    const int tid  = threadIdx.x;
    const int lane = tid & 31;
    const int wid  = tid >> 5;
    const int q    = wid & 3;      // n-column group
    const int r    = wid >> 2;     // m-half (tokens r*64..r*64+63)
    const uint32_t wsb = smem_u32(ws);

    // ---- one-time setup ----
    for (int i = tid; i < 64; i += THREADS) {
        rwd_s[i] = read_w[2 * i] - read_w[2 * i + 1];
        float b1 = b_stack[64 + i];
        b1_s[i] = b1;
        bd_s[i] = b_stack[i] - b1;
    }
    for (int i = tid; i < 16 * 64; i += THREADS) emb_s[i] = emb[i];

    // Wcat bf16 hi/lo tiles: row n (128B = 64 bf16), XOR-swizzled 16B units.
    // n<64: W1 rows; n>=64: W0-W1 rows. Process 2 k at a time.
    for (int i = tid; i < 128 * 32; i += THREADS) {
        int n = i >> 5, kp = (i & 31) * 2;
        float v0, v1;
        if (n < 64) {
            v0 = w_stack[4096 + n * 64 + kp];
            v1 = w_stack[4096 + n * 64 + kp + 1];
        } else {
            int m = n - 64;
            v0 = w_stack[m * 64 + kp]     - w_stack[4096 + m * 64 + kp];
            v1 = w_stack[m * 64 + kp + 1] - w_stack[4096 + m * 64 + kp + 1];
        }
        uint32_t h = cvt2bf(v0, v1);
        float h0 = __uint_as_float(h << 16);
        float h1 = __uint_as_float(h & 0xffff0000u);
        uint32_t l = cvt2bf(v0 - h0, v1 - h1);
        int off = n * 128 + ((((kp >> 3) ^ (n & 7))) << 4) + (kp & 7) * 2;
        *(uint32_t*)(ws + off)         = h;
        *(uint32_t*)(ws + 16384 + off) = l;
    }
    __syncthreads();

    // ---- load B fragments into registers (kept for whole kernel) ----
    // warp q owns n8-tiles {2q, 2q+1, 2q+8, 2q+9}; nti 0,1 = h1 cols, 2,3 = hd cols
    uint32_t Bh[4][4][2], Bl[4][4][2];
    #pragma unroll
    for (int nti = 0; nti < 4; nti++) {
        int nt = 2 * q + (nti & 1) + ((nti >> 1) << 3);
        #pragma unroll
        for (int k = 0; k < 4; k++) {
            int row  = nt * 8 + (lane & 7);
            int unit = k * 2 + ((lane >> 3) & 1);
            uint32_t addr = wsb + row * 128 + ((unit ^ (row & 7)) << 4);
            ldsm_x2(Bh[nti][k], addr);
            ldsm_x2(Bl[nti][k], addr + 16384);
        }
    }
    __syncthreads();   // ws now free for A tiles

    const int grp = lane >> 2, tc = lane & 3;

    for (int tile = blockIdx.x; tile < NTILES; tile += GRID)
    {
        // ---- convert phase: LDG x, +emb, gate partials, bf16 hi/lo STS ----
        {
            const float4* src = (const float4*)x + (size_t)tile * (TILE_M * 64 / 4);
            #pragma unroll
            for (int i = 0; i < 8; i++) {
                int j = tid + i * THREADS;       // float4 index in tile
                int t = j >> 4, c = j & 15;      // token, chunk (k = 4c..4c+3)
                float4 v = src[j];
                const float* ep = &emb_s[(t & 15) * 64 + c * 4];
                v.x += ep[0]; v.y += ep[1]; v.z += ep[2]; v.w += ep[3];
                // gate partial: 16 lanes of this token reduce via shfl tree
                const float* rp = &rwd_s[c * 4];
                float p = v.x * rp[0] + v.y * rp[1] + v.z * rp[2] + v.w * rp[3];
                p += __shfl_xor_sync(0xffffffffu, p, 1);
                p += __shfl_xor_sync(0xffffffffu, p, 2);
                p += __shfl_xor_sync(0xffffffffu, p, 4);
                p += __shfl_xor_sync(0xffffffffu, p, 8);
                if ((lane & 15) == 0) logit_s[t] = p;
                // bf16 split
                uint32_t h0 = cvt2bf(v.x, v.y);
                uint32_t h1 = cvt2bf(v.z, v.w);
                float hx = __uint_as_float(h0 << 16), hy = __uint_as_float(h0 & 0xffff0000u);
                float hz = __uint_as_float(h1 << 16), hw = __uint_as_float(h1 & 0xffff0000u);
                uint32_t l0 = cvt2bf(v.x - hx, v.y - hy);
                uint32_t l1 = cvt2bf(v.z - hz, v.w - hw);
                int off = t * 128 + (((c >> 1) ^ (t & 7)) << 4) + (c & 1) * 8;
                *(uint2*)(ws + off)         = make_uint2(h0, h1);
                *(uint2*)(ws + 16384 + off) = make_uint2(l0, l1);
            }
        }
        __syncthreads();

        // ---- MMA phase: acc[m][n][4], warp tile 64 tok x 32 out, 3 passes ----
        float acc[4][4][4];
        #pragma unroll
        for (int m = 0; m < 4; m++)
            #pragma unroll
            for (int n = 0; n < 4; n++)
                #pragma unroll
                for (int e = 0; e < 4; e++) acc[m][n][e] = 0.f;

        #pragma unroll
        for (int k = 0; k < 4; k++) {
            #pragma unroll
            for (int m = 0; m < 4; m++) {
                int tok  = r * 64 + m * 16 + (lane & 15);
                int unit = k * 2 + (lane >> 4);
                uint32_t addr = wsb + tok * 128 + ((unit ^ (tok & 7)) << 4);
                uint32_t Ahi[4], Alo[4];
                ldsm_x4(Ahi, addr);
                ldsm_x4(Alo, addr + 16384);
                #pragma unroll
                for (int n = 0; n < 4; n++) mma_bf16(acc[m][n], Ahi, Bh[n][k]);
                #pragma unroll
                for (int n = 0; n < 4; n++) mma_bf16(acc[m][n], Ahi, Bl[n][k]);
                #pragma unroll
                for (int n = 0; n < 4; n++) mma_bf16(acc[m][n], Alo, Bh[n][k]);
            }
        }

        // ---- epilogue: gate combine + direct STG ----
        {
            float* outb = out + (size_t)tile * (TILE_M * 64);
            #pragma unroll
            for (int m = 0; m < 4; m++) {
                int t0 = r * 64 + m * 16 + grp;
                int t1 = t0 + 8;
                float lg0 = logit_s[t0], lg1 = logit_s[t1];
                float a00 = 1.f / (1.f + __expf(-lg0));
                float a01 = 1.f / (1.f + __expf(-lg1));
                #pragma unroll
                for (int np = 0; np < 2; np++) {
                    int o = (2 * q + np) * 8 + tc * 2;
                    float2 b1v = *(const float2*)&b1_s[o];
                    float2 bdv = *(const float2*)&bd_s[o];
                    const float* h1p = acc[m][np];
                    const float* hdp = acc[m][np + 2];
                    float2 r0, r1;
                    r0.x = fmaf(a00, hdp[0] + bdv.x, h1p[0] + b1v.x);
                    r0.y = fmaf(a00, hdp[1] + bdv.y, h1p[1] + b1v.y);
                    r1.x = fmaf(a01, hdp[2] + bdv.x, h1p[2] + b1v.x);
                    r1.y = fmaf(a01, hdp[3] + bdv.y, h1p[3] + b1v.y);
                    *(float2*)&outb[t0 * 64 + o] = r0;
                    *(float2*)&outb[t1 * 64 + o] = r1;
                }
            }
        }
        __syncthreads();   // A tile + logits reused next iteration
    }
}

extern "C" void kernel_launch(void* const* d_in, const int* in_sizes, int n_in,
                              void* d_out, int out_size)
{
    const float* x       = (const float*)d_in[0];
    const float* emb     = (const float*)d_in[1];
    const float* read_w  = (const float*)d_in[2];
    const float* w_stack = (const float*)d_in[3];
    const float* b_stack = (const float*)d_in[4];
    float* out = (float*)d_out;

    sgl_mma_kernel<<<GRID, THREADS>>>(x, emb, read_w, w_stack, b_stack, out);
}